// round 12
// baseline (speedup 1.0000x reference)
#include <cuda_runtime.h>
#include <cuda_bf16.h>
#include <mma.h>
#include <math.h>
#include <stdint.h>

using namespace nvcuda;

// ---------------------------------------------------------------------------
// DenseGAT: 2-layer GAT, N=100000 nodes, E=1600000 edges, 256 -> 64 -> 40
// bf16-split WMMA GEMM (2D warp tile, trunc split, 2 CTAs/SM, A-prefetch)
// + fused logits; CSR-by-dst; f32x2 64-bit gather aggregation.
// ---------------------------------------------------------------------------

#define MAX_NODES 100000
#define MAX_EDGES 1600000
#define SCAN_CHUNK 512
#define MAX_BLOCKS_SCAN 256

__device__ float g_z   [MAX_NODES * 64];
__device__ float g_h   [MAX_NODES * 64];
__device__ float g_el  [MAX_NODES];
__device__ float g_er  [MAX_NODES];
__device__ int   g_deg [MAX_NODES];
__device__ int   g_scan[MAX_NODES];
__device__ int   g_off [MAX_NODES + 1];
__device__ int   g_cur [MAX_NODES];
__device__ int   g_srcs[MAX_EDGES];
__device__ int   g_bsum[MAX_BLOCKS_SCAN];
__device__ int   g_boff[MAX_BLOCKS_SCAN];

// bf16 hi/lo W planes, row-major padded: layer1 [256][64], layer2 [64][48]
__device__ __align__(16) __nv_bfloat16 g_bt1h[256 * 64];
__device__ __align__(16) __nv_bfloat16 g_bt1l[256 * 64];
__device__ __align__(16) __nv_bfloat16 g_bt2h[64 * 48];
__device__ __align__(16) __nv_bfloat16 g_bt2l[64 * 48];

// ----------------------------- helpers ------------------------------------

__device__ __forceinline__ unsigned long long pack2(float a) {
    unsigned long long r;
    asm("mov.b64 %0, {%1, %1};" : "=l"(r) : "f"(a));
    return r;
}
__device__ __forceinline__ void fma2(unsigned long long& d,
                                     unsigned long long a, unsigned long long b) {
    asm("fma.rn.f32x2 %0, %1, %2, %0;" : "+l"(d) : "l"(a), "l"(b));
}
__device__ __forceinline__ float2 unpack2(unsigned long long v) {
    float2 f;
    asm("mov.b64 {%0, %1}, %2;" : "=f"(f.x), "=f"(f.y) : "l"(v));
    return f;
}

__device__ __forceinline__ float warp_max(float v) {
#pragma unroll
    for (int o = 16; o > 0; o >>= 1)
        v = fmaxf(v, __shfl_xor_sync(0xffffffffu, v, o));
    return v;
}
__device__ __forceinline__ float warp_sum(float v) {
#pragma unroll
    for (int o = 16; o > 0; o >>= 1)
        v += __shfl_xor_sync(0xffffffffu, v, o);
    return v;
}

// ----------------------------- W convert ----------------------------------

__global__ void wconv_kernel(const float* __restrict__ W, int K, int NOUT, int NPAD,
                             __nv_bfloat16* __restrict__ oh, __nv_bfloat16* __restrict__ ol) {
    int idx = blockIdx.x * blockDim.x + threadIdx.x;
    if (idx >= K * NPAD) return;
    int k = idx / NPAD;
    int n = idx % NPAD;
    float v = (n < NOUT) ? W[k * NOUT + n] : 0.f;
    __nv_bfloat16 h = __float2bfloat16(v);
    __nv_bfloat16 l = __float2bfloat16(v - __bfloat162float(h));
    oh[idx] = h;
    ol[idx] = l;
}

// ----------------------------- CSR build ----------------------------------

__global__ void hist_kernel(const int* __restrict__ dst, int E) {
    int i = blockIdx.x * blockDim.x + threadIdx.x;
    if (i < E) atomicAdd(&g_deg[dst[i]], 1);
}

__global__ void scan_phase1(int n) {
    __shared__ int sm[SCAN_CHUNK];
    int i = blockIdx.x * SCAN_CHUNK + threadIdx.x;
    int d = (i < n) ? g_deg[i] : 0;
    if (i < n) g_deg[i] = 0;
    sm[threadIdx.x] = d;
    __syncthreads();
#pragma unroll
    for (int o = 1; o < SCAN_CHUNK; o <<= 1) {
        int t = (threadIdx.x >= o) ? sm[threadIdx.x - o] : 0;
        __syncthreads();
        sm[threadIdx.x] += t;
        __syncthreads();
    }
    if (i < n) g_scan[i] = sm[threadIdx.x];
    if (threadIdx.x == SCAN_CHUNK - 1) g_bsum[blockIdx.x] = sm[SCAN_CHUNK - 1];
}

__global__ void scan_phase2(int nb) {
    int lane = threadIdx.x;
    int base = lane * 8;
    int v[8];
    int s = 0;
#pragma unroll
    for (int j = 0; j < 8; j++) {
        int x = (base + j < nb) ? g_bsum[base + j] : 0;
        v[j] = s;
        s += x;
    }
    int t = s;
#pragma unroll
    for (int o = 1; o < 32; o <<= 1) {
        int u = __shfl_up_sync(0xffffffffu, t, o);
        if (lane >= o) t += u;
    }
    int excl = t - s;
#pragma unroll
    for (int j = 0; j < 8; j++)
        if (base + j < nb) g_boff[base + j] = excl + v[j];
}

__global__ void scan_phase3(int n) {
    int i = blockIdx.x * blockDim.x + threadIdx.x;
    if (i < n) {
        int v = g_scan[i] + g_boff[i >> 9];
        g_off[i + 1] = v;
        if (i + 1 < n) g_cur[i + 1] = v;
    }
    if (i == 0) { g_off[0] = 0; g_cur[0] = 0; }
}

__global__ void scatter_kernel(const int* __restrict__ src, const int* __restrict__ dst, int E) {
    int i = blockIdx.x * blockDim.x + threadIdx.x;
    if (i >= E) return;
    int pos = atomicAdd(&g_cur[dst[i]], 1);
    g_srcs[pos] = src[i];
}

// ----------------------------- WMMA GEMM + fused logits --------------------
// (round-11 version, unchanged: measured 64.8us)

template<int K, int NOUT, int NPAD, int COLW>
__global__ void __launch_bounds__(256, 2)
gemm_wmma_kernel(const float* __restrict__ A,
                 const __nv_bfloat16* __restrict__ Bh,
                 const __nv_bfloat16* __restrict__ Bl,
                 const float* __restrict__ al, const float* __restrict__ ar,
                 float* __restrict__ Z, int M) {
    constexpr int CH  = K / 64;
    constexpr int ROWG = 8 / COLW;
    constexpr int RPW  = 128 / ROWG;
    constexpr int RF   = RPW / 16;
    constexpr int CT   = NPAD / 16 / COLW;
    constexpr int CWID = NPAD / COLW;
    constexpr int ALD = 136;
    constexpr int BLD = NPAD + 8;
    constexpr int ABYTES = 128 * ALD * 2;

    __shared__ __align__(16) unsigned char sraw[ABYTES + 128 * BLD * 2];
    __nv_bfloat16 (*As)[ALD] = (__nv_bfloat16(*)[ALD])sraw;
    __nv_bfloat16 (*Bs)[BLD] = (__nv_bfloat16(*)[BLD])(sraw + ABYTES);

    int tid  = threadIdx.x;
    int wid  = tid >> 5;
    int lane = tid & 31;
    int m0   = blockIdx.x * 128;
    int cw   = wid % COLW;
    int rw   = wid / COLW;

    wmma::fragment<wmma::accumulator, 16, 16, 16, float> c[RF][CT];
#pragma unroll
    for (int rf = 0; rf < RF; rf++)
#pragma unroll
        for (int ct = 0; ct < CT; ct++)
            wmma::fill_fragment(c[rf][ct], 0.f);

    float4 pa[8];
#pragma unroll
    for (int t = 0; t < 8; t++) {
        int idx = tid + t * 256;
        int r   = idx >> 4;
        int c4  = (idx & 15) * 4;
        int row = m0 + r;
        pa[t] = make_float4(0.f, 0.f, 0.f, 0.f);
        if (row < M) pa[t] = *(const float4*)&A[(size_t)row * K + c4];
    }

    for (int ch = 0; ch < CH; ch++) {
#pragma unroll
        for (int t = 0; t < 8; t++) {
            int idx = tid + t * 256;
            int r   = idx >> 4;
            int c4  = (idx & 15) * 4;
            float4 v = pa[t];
            unsigned bx = __float_as_uint(v.x) & 0xFFFF0000u;
            unsigned by = __float_as_uint(v.y) & 0xFFFF0000u;
            unsigned bz = __float_as_uint(v.z) & 0xFFFF0000u;
            unsigned bw = __float_as_uint(v.w) & 0xFFFF0000u;
            unsigned h01 = __byte_perm(__float_as_uint(v.x), __float_as_uint(v.y), 0x7632);
            unsigned h23 = __byte_perm(__float_as_uint(v.z), __float_as_uint(v.w), 0x7632);
            *(unsigned*)&As[r][c4]     = h01;
            *(unsigned*)&As[r][c4 + 2] = h23;
            *(__nv_bfloat162*)&As[r][64 + c4] =
                __floats2bfloat162_rn(v.x - __uint_as_float(bx), v.y - __uint_as_float(by));
            *(__nv_bfloat162*)&As[r][64 + c4 + 2] =
                __floats2bfloat162_rn(v.z - __uint_as_float(bz), v.w - __uint_as_float(bw));
        }
        {
            constexpr int R8 = NPAD / 8;
            int k0 = ch * 64;
            for (int i = tid; i < 64 * R8 * 2; i += 256) {
                int plane = i / (64 * R8);
                int j     = i % (64 * R8);
                int k     = j / R8;
                int b8    = j % R8;
                const __nv_bfloat16* sp = plane ? Bl : Bh;
                uint4 v = *(const uint4*)&sp[(size_t)(k0 + k) * NPAD + b8 * 8];
                *(uint4*)&Bs[plane * 64 + k][b8 * 8] = v;
            }
        }
        __syncthreads();

        if (ch + 1 < CH) {
            int k0n = (ch + 1) * 64;
#pragma unroll
            for (int t = 0; t < 8; t++) {
                int idx = tid + t * 256;
                int r   = idx >> 4;
                int c4  = (idx & 15) * 4;
                int row = m0 + r;
                pa[t] = make_float4(0.f, 0.f, 0.f, 0.f);
                if (row < M) pa[t] = *(const float4*)&A[(size_t)row * K + k0n + c4];
            }
        }

#pragma unroll
        for (int k16 = 0; k16 < 4; k16++) {
            wmma::fragment<wmma::matrix_a, 16, 16, 16, __nv_bfloat16, wmma::row_major> ah[RF], alo[RF];
#pragma unroll
            for (int rf = 0; rf < RF; rf++) {
                wmma::load_matrix_sync(ah[rf],  &As[rw * RPW + rf * 16][k16 * 16],      ALD);
                wmma::load_matrix_sync(alo[rf], &As[rw * RPW + rf * 16][64 + k16 * 16], ALD);
            }
#pragma unroll
            for (int ct = 0; ct < CT; ct++) {
                int cb = cw * CWID + ct * 16;
                wmma::fragment<wmma::matrix_b, 16, 16, 16, __nv_bfloat16, wmma::row_major> bh, bl;
                wmma::load_matrix_sync(bh, &Bs[k16 * 16][cb],      BLD);
                wmma::load_matrix_sync(bl, &Bs[64 + k16 * 16][cb], BLD);
#pragma unroll
                for (int rf = 0; rf < RF; rf++) {
                    wmma::mma_sync(c[rf][ct], ah[rf],  bh, c[rf][ct]);
                    wmma::mma_sync(c[rf][ct], ah[rf],  bl, c[rf][ct]);
                    wmma::mma_sync(c[rf][ct], alo[rf], bh, c[rf][ct]);
                }
            }
        }
        __syncthreads();
    }

    float (*Cbuf)[16][16] = (float(*)[16][16])sraw;
    float (*buf)[16] = Cbuf[wid];
    float* elbuf = (float*)(sraw + ABYTES);
    float* erbuf = elbuf + 128;
    if (tid < 128) { elbuf[tid] = 0.f; erbuf[tid] = 0.f; }
    __syncthreads();

#pragma unroll
    for (int rf = 0; rf < RF; rf++) {
        float elp = 0.f, erp = 0.f;
#pragma unroll
        for (int ct = 0; ct < CT; ct++) {
            wmma::store_matrix_sync(&buf[0][0], c[rf][ct], 16, wmma::mem_row_major);
            __syncwarp();
            int cb = cw * CWID + ct * 16;
            if (lane < 16) {
                int row = m0 + rw * RPW + rf * 16 + lane;
                if (row < M) {
#pragma unroll
                    for (int j = 0; j < 16; j++) {
                        int col = cb + j;
                        if (col < NOUT) {
                            float v = buf[lane][j];
                            elp += v * al[col];
                            erp += v * ar[col];
                        }
                    }
                }
            }
#pragma unroll
            for (int rep = 0; rep < 2; rep++) {
                int idx = lane + rep * 32;
                int r   = idx >> 2;
                int c4  = idx & 3;
                int row = m0 + rw * RPW + rf * 16 + r;
                int col = cb + c4 * 4;
                if (row < M && col < NOUT)
                    *(float4*)&Z[(size_t)row * NOUT + col] = *(float4*)&buf[r][c4 * 4];
            }
            __syncwarp();
        }
        if (lane < 16) {
            int lrow = rw * RPW + rf * 16 + lane;
            atomicAdd(&elbuf[lrow], elp);
            atomicAdd(&erbuf[lrow], erp);
        }
    }
    __syncthreads();
    if (tid < 128) {
        int row = m0 + tid;
        if (row < M) { g_el[row] = elbuf[tid]; g_er[row] = erbuf[tid]; }
    }
}

// --------------------- fused softmax + aggregation ------------------------
// Gather is 64-bit: each lane owns a column pair, LDG.64 per edge, f32x2 FMA.

__global__ void fused_agg1_kernel(const float* __restrict__ Z, const float* __restrict__ b,
                                  float* __restrict__ H, int n, float neg_slope) {
    int node = (blockIdx.x * blockDim.x + threadIdx.x) >> 5;
    int lane = threadIdx.x & 31;
    if (node >= n) return;
    int start = g_off[node], end = g_off[node + 1];
    int deg   = end - start;
    float erd = g_er[node];
    int c2 = 2 * lane;   // this lane's column pair

    unsigned long long acc0 = 0ull, acc1 = 0ull;
    float sum = 0.f;

    if (deg <= 32) {
        bool v = lane < deg;
        int   s = v ? g_srcs[start + lane] : 0;
        float e = v ? (g_el[s] + erd) : -3.4e38f;
        e = (e > 0.f) ? e : neg_slope * e;
        float m = warp_max(e);
        float w = v ? expf(e - m) : 0.f;
        sum = w;
        int cnt8 = (deg + 7) & ~7;
        for (int j = 0; j < cnt8; j += 8) {
#pragma unroll
            for (int jj = 0; jj < 8; jj += 2) {
                int   s0 = __shfl_sync(0xffffffffu, s, j + jj);
                float w0 = __shfl_sync(0xffffffffu, w, j + jj);
                int   s1 = __shfl_sync(0xffffffffu, s, j + jj + 1);
                float w1 = __shfl_sync(0xffffffffu, w, j + jj + 1);
                unsigned long long z0 = *(const unsigned long long*)&Z[(long long)s0 * 64 + c2];
                unsigned long long z1 = *(const unsigned long long*)&Z[(long long)s1 * 64 + c2];
                fma2(acc0, pack2(w0), z0);
                fma2(acc1, pack2(w1), z1);
            }
        }
    } else {
        float m = -3.4e38f;
        for (int i = start + lane; i < end; i += 32) {
            float e = g_el[g_srcs[i]] + erd;
            e = (e > 0.f) ? e : neg_slope * e;
            m = fmaxf(m, e);
        }
        m = warp_max(m);
        for (int c = start; c < end; c += 32) {
            int idx = c + lane;
            bool v = idx < end;
            int   s = v ? g_srcs[idx] : 0;
            float e = v ? (g_el[s] + erd) : -3.4e38f;
            e = (e > 0.f) ? e : neg_slope * e;
            float w = v ? expf(e - m) : 0.f;
            sum += w;
            int cnt  = min(32, end - c);
            int cnt8 = (cnt + 7) & ~7;
            for (int j = 0; j < cnt8; j += 8) {
#pragma unroll
                for (int jj = 0; jj < 8; jj += 2) {
                    int   s0 = __shfl_sync(0xffffffffu, s, j + jj);
                    float w0 = __shfl_sync(0xffffffffu, w, j + jj);
                    int   s1 = __shfl_sync(0xffffffffu, s, j + jj + 1);
                    float w1 = __shfl_sync(0xffffffffu, w, j + jj + 1);
                    unsigned long long z0 = *(const unsigned long long*)&Z[(long long)s0 * 64 + c2];
                    unsigned long long z1 = *(const unsigned long long*)&Z[(long long)s1 * 64 + c2];
                    fma2(acc0, pack2(w0), z0);
                    fma2(acc1, pack2(w1), z1);
                }
            }
        }
    }

    sum = warp_sum(sum);
    float sinv = (deg > 0) ? 1.f / sum : 0.f;
    float2 a0 = unpack2(acc0);
    float2 a1 = unpack2(acc1);
    float vx = (a0.x + a1.x) * sinv + b[c2];
    float vy = (a0.y + a1.y) * sinv + b[c2 + 1];
    float2 r = make_float2((vx > 0.f) ? vx : 0.f, (vy > 0.f) ? vy : 0.f);
    *(float2*)&H[(long long)node * 64 + c2] = r;
}

// Layer 2: F = 40; lanes 0..19 own column pairs; fused bias + log_softmax.
__global__ void fused_agg2_kernel(const float* __restrict__ Z, const float* __restrict__ b,
                                  float* __restrict__ out, int n, float neg_slope) {
    int node = (blockIdx.x * blockDim.x + threadIdx.x) >> 5;
    int lane = threadIdx.x & 31;
    if (node >= n) return;
    int start = g_off[node], end = g_off[node + 1];
    int deg   = end - start;
    float erd = g_er[node];
    bool act = lane < 20;
    int c2 = act ? 2 * lane : 0;

    unsigned long long acc0 = 0ull, acc1 = 0ull;
    float sum = 0.f;

    if (deg <= 32) {
        bool v = lane < deg;
        int   s = v ? g_srcs[start + lane] : 0;
        float e = v ? (g_el[s] + erd) : -3.4e38f;
        e = (e > 0.f) ? e : neg_slope * e;
        float m = warp_max(e);
        float w = v ? expf(e - m) : 0.f;
        sum = w;
        int cnt8 = (deg + 7) & ~7;
        for (int j = 0; j < cnt8; j += 8) {
#pragma unroll
            for (int jj = 0; jj < 8; jj += 2) {
                int   s0 = __shfl_sync(0xffffffffu, s, j + jj);
                float w0 = __shfl_sync(0xffffffffu, w, j + jj);
                int   s1 = __shfl_sync(0xffffffffu, s, j + jj + 1);
                float w1 = __shfl_sync(0xffffffffu, w, j + jj + 1);
                unsigned long long z0 = *(const unsigned long long*)&Z[(long long)s0 * 40 + c2];
                unsigned long long z1 = *(const unsigned long long*)&Z[(long long)s1 * 40 + c2];
                fma2(acc0, pack2(w0), z0);
                fma2(acc1, pack2(w1), z1);
            }
        }
    } else {
        float m = -3.4e38f;
        for (int i = start + lane; i < end; i += 32) {
            float e = g_el[g_srcs[i]] + erd;
            e = (e > 0.f) ? e : neg_slope * e;
            m = fmaxf(m, e);
        }
        m = warp_max(m);
        for (int c = start; c < end; c += 32) {
            int idx = c + lane;
            bool v = idx < end;
            int   s = v ? g_srcs[idx] : 0;
            float e = v ? (g_el[s] + erd) : -3.4e38f;
            e = (e > 0.f) ? e : neg_slope * e;
            float w = v ? expf(e - m) : 0.f;
            sum += w;
            int cnt  = min(32, end - c);
            int cnt8 = (cnt + 7) & ~7;
            for (int j = 0; j < cnt8; j += 8) {
#pragma unroll
                for (int jj = 0; jj < 8; jj += 2) {
                    int   s0 = __shfl_sync(0xffffffffu, s, j + jj);
                    float w0 = __shfl_sync(0xffffffffu, w, j + jj);
                    int   s1 = __shfl_sync(0xffffffffu, s, j + jj + 1);
                    float w1 = __shfl_sync(0xffffffffu, w, j + jj + 1);
                    unsigned long long z0 = *(const unsigned long long*)&Z[(long long)s0 * 40 + c2];
                    unsigned long long z1 = *(const unsigned long long*)&Z[(long long)s1 * 40 + c2];
                    fma2(acc0, pack2(w0), z0);
                    fma2(acc1, pack2(w1), z1);
                }
            }
        }
    }

    sum = warp_sum(sum);
    float sinv = (deg > 0) ? 1.f / sum : 0.f;
    float2 a0 = unpack2(acc0);
    float2 a1 = unpack2(acc1);
    float vx = act ? ((a0.x + a1.x) * sinv + b[c2])     : -3.4e38f;
    float vy = act ? ((a0.y + a1.y) * sinv + b[c2 + 1]) : -3.4e38f;

    float mx = warp_max(fmaxf(vx, vy));
    float se = warp_sum(act ? (expf(vx - mx) + expf(vy - mx)) : 0.f);
    float lse = mx + logf(se);

    if (act)
        *(float2*)&out[(long long)node * 40 + c2] = make_float2(vx - lse, vy - lse);
}

// ----------------------------- host launch ---------------------------------

extern "C" void kernel_launch(void* const* d_in, const int* in_sizes, int n_in,
                              void* d_out, int out_size) {
    const float* feat = (const float*)d_in[0];
    const int*   src  = (const int*)  d_in[1];
    const int*   dst  = (const int*)  d_in[2];
    const float* W1   = (const float*)d_in[3];
    const float* b1   = (const float*)d_in[4];
    const float* al1  = (const float*)d_in[5];
    const float* ar1  = (const float*)d_in[6];
    const float* W2   = (const float*)d_in[7];
    const float* b2   = (const float*)d_in[8];
    const float* al2  = (const float*)d_in[9];
    const float* ar2  = (const float*)d_in[10];
    float* out = (float*)d_out;

    const int IN = 256;
    int n = in_sizes[0] / IN;   // 100000
    int E = in_sizes[1];        // 1600000

    float* zp; cudaGetSymbolAddress((void**)&zp, g_z);
    float* hp; cudaGetSymbolAddress((void**)&hp, g_h);
    __nv_bfloat16 *bt1h, *bt1l, *bt2h, *bt2l;
    cudaGetSymbolAddress((void**)&bt1h, g_bt1h);
    cudaGetSymbolAddress((void**)&bt1l, g_bt1l);
    cudaGetSymbolAddress((void**)&bt2h, g_bt2h);
    cudaGetSymbolAddress((void**)&bt2l, g_bt2l);

    const float NEG_SLOPE = 0.2f;
    int mb128 = (n + 127) / 128;
    int nb_scan = (n + SCAN_CHUNK - 1) / SCAN_CHUNK;

    // gemm1 at stream launch index 3 (profiler's capture slot).
    wconv_kernel<<<(256 * 64 + 255) / 256, 256>>>(W1, 256, 64, 64, bt1h, bt1l);         // 0
    hist_kernel<<<(E + 255) / 256, 256>>>(dst, E);                                      // 1
    scan_phase1<<<nb_scan, SCAN_CHUNK>>>(n);                                            // 2
    gemm_wmma_kernel<256, 64, 64, 2><<<mb128, 256>>>(feat, bt1h, bt1l, al1, ar1, zp, n);// 3 <- profiled
    wconv_kernel<<<(64 * 48 + 255) / 256, 256>>>(W2, 64, 40, 48, bt2h, bt2l);           // 4
    scan_phase2<<<1, 32>>>(nb_scan);                                                    // 5
    scan_phase3<<<(n + 255) / 256, 256>>>(n);                                           // 6
    scatter_kernel<<<(E + 255) / 256, 256>>>(src, dst, E);                              // 7

    fused_agg1_kernel<<<(n * 32 + 255) / 256, 256>>>(zp, b1, hp, n, NEG_SLOPE);         // 8
    gemm_wmma_kernel<64, 40, 48, 1><<<mb128, 256>>>(hp, bt2h, bt2l, al2, ar2, zp, n);   // 9
    fused_agg2_kernel<<<(n * 32 + 255) / 256, 256>>>(zp, b2, out, n, NEG_SLOPE);        // 10
}

// round 13
// speedup vs baseline: 1.0365x; 1.0365x over previous
#include <cuda_runtime.h>
#include <cuda_bf16.h>
#include <mma.h>
#include <math.h>
#include <stdint.h>

using namespace nvcuda;

// ---------------------------------------------------------------------------
// DenseGAT: 2-layer GAT, N=100000 nodes, E=1600000 edges, 256 -> 64 -> 40
// bf16-split WMMA GEMM (2D warp tile, trunc split, STS.64 A-stores, 2 CTAs/SM,
// A-prefetch) + fused logits; CSR-by-dst; round-9 gather agg (frozen best).
// ---------------------------------------------------------------------------

#define MAX_NODES 100000
#define MAX_EDGES 1600000
#define SCAN_CHUNK 512
#define MAX_BLOCKS_SCAN 256

__device__ float g_z   [MAX_NODES * 64];
__device__ float g_h   [MAX_NODES * 64];
__device__ float g_el  [MAX_NODES];
__device__ float g_er  [MAX_NODES];
__device__ int   g_deg [MAX_NODES];
__device__ int   g_scan[MAX_NODES];
__device__ int   g_off [MAX_NODES + 1];
__device__ int   g_cur [MAX_NODES];
__device__ int   g_srcs[MAX_EDGES];
__device__ int   g_bsum[MAX_BLOCKS_SCAN];
__device__ int   g_boff[MAX_BLOCKS_SCAN];

// bf16 hi/lo W planes, row-major padded: layer1 [256][64], layer2 [64][48]
__device__ __align__(16) __nv_bfloat16 g_bt1h[256 * 64];
__device__ __align__(16) __nv_bfloat16 g_bt1l[256 * 64];
__device__ __align__(16) __nv_bfloat16 g_bt2h[64 * 48];
__device__ __align__(16) __nv_bfloat16 g_bt2l[64 * 48];

__device__ __forceinline__ float warp_max(float v) {
#pragma unroll
    for (int o = 16; o > 0; o >>= 1)
        v = fmaxf(v, __shfl_xor_sync(0xffffffffu, v, o));
    return v;
}
__device__ __forceinline__ float warp_sum(float v) {
#pragma unroll
    for (int o = 16; o > 0; o >>= 1)
        v += __shfl_xor_sync(0xffffffffu, v, o);
    return v;
}

// ----------------------------- W convert ----------------------------------

__global__ void wconv_kernel(const float* __restrict__ W, int K, int NOUT, int NPAD,
                             __nv_bfloat16* __restrict__ oh, __nv_bfloat16* __restrict__ ol) {
    int idx = blockIdx.x * blockDim.x + threadIdx.x;
    if (idx >= K * NPAD) return;
    int k = idx / NPAD;
    int n = idx % NPAD;
    float v = (n < NOUT) ? W[k * NOUT + n] : 0.f;
    __nv_bfloat16 h = __float2bfloat16(v);
    __nv_bfloat16 l = __float2bfloat16(v - __bfloat162float(h));
    oh[idx] = h;
    ol[idx] = l;
}

// ----------------------------- CSR build ----------------------------------

__global__ void hist_kernel(const int* __restrict__ dst, int E) {
    int i = blockIdx.x * blockDim.x + threadIdx.x;
    if (i < E) atomicAdd(&g_deg[dst[i]], 1);
}

__global__ void scan_phase1(int n) {
    __shared__ int sm[SCAN_CHUNK];
    int i = blockIdx.x * SCAN_CHUNK + threadIdx.x;
    int d = (i < n) ? g_deg[i] : 0;
    if (i < n) g_deg[i] = 0;
    sm[threadIdx.x] = d;
    __syncthreads();
#pragma unroll
    for (int o = 1; o < SCAN_CHUNK; o <<= 1) {
        int t = (threadIdx.x >= o) ? sm[threadIdx.x - o] : 0;
        __syncthreads();
        sm[threadIdx.x] += t;
        __syncthreads();
    }
    if (i < n) g_scan[i] = sm[threadIdx.x];
    if (threadIdx.x == SCAN_CHUNK - 1) g_bsum[blockIdx.x] = sm[SCAN_CHUNK - 1];
}

__global__ void scan_phase2(int nb) {
    int lane = threadIdx.x;
    int base = lane * 8;
    int v[8];
    int s = 0;
#pragma unroll
    for (int j = 0; j < 8; j++) {
        int x = (base + j < nb) ? g_bsum[base + j] : 0;
        v[j] = s;
        s += x;
    }
    int t = s;
#pragma unroll
    for (int o = 1; o < 32; o <<= 1) {
        int u = __shfl_up_sync(0xffffffffu, t, o);
        if (lane >= o) t += u;
    }
    int excl = t - s;
#pragma unroll
    for (int j = 0; j < 8; j++)
        if (base + j < nb) g_boff[base + j] = excl + v[j];
}

__global__ void scan_phase3(int n) {
    int i = blockIdx.x * blockDim.x + threadIdx.x;
    if (i < n) {
        int v = g_scan[i] + g_boff[i >> 9];
        g_off[i + 1] = v;
        if (i + 1 < n) g_cur[i + 1] = v;
    }
    if (i == 0) { g_off[0] = 0; g_cur[0] = 0; }
}

__global__ void scatter_kernel(const int* __restrict__ src, const int* __restrict__ dst, int E) {
    int i = blockIdx.x * blockDim.x + threadIdx.x;
    if (i >= E) return;
    int pos = atomicAdd(&g_cur[dst[i]], 1);
    g_srcs[pos] = src[i];
}

// ----------------------------- WMMA GEMM + fused logits --------------------
// 3-term bf16 split: A*W ~= Ah*Bh + Ah*Bl + Al*Bh (fp32 accum).
// A hi = truncated bf16; STS.64-packed tile stores. 2D warp tile, 2 CTAs/SM.

template<int K, int NOUT, int NPAD, int COLW>
__global__ void __launch_bounds__(256, 2)
gemm_wmma_kernel(const float* __restrict__ A,
                 const __nv_bfloat16* __restrict__ Bh,
                 const __nv_bfloat16* __restrict__ Bl,
                 const float* __restrict__ al, const float* __restrict__ ar,
                 float* __restrict__ Z, int M) {
    constexpr int CH  = K / 64;
    constexpr int ROWG = 8 / COLW;
    constexpr int RPW  = 128 / ROWG;
    constexpr int RF   = RPW / 16;
    constexpr int CT   = NPAD / 16 / COLW;
    constexpr int CWID = NPAD / COLW;
    constexpr int ALD = 136;
    constexpr int BLD = NPAD + 8;
    constexpr int ABYTES = 128 * ALD * 2;

    __shared__ __align__(16) unsigned char sraw[ABYTES + 128 * BLD * 2];
    __nv_bfloat16 (*As)[ALD] = (__nv_bfloat16(*)[ALD])sraw;
    __nv_bfloat16 (*Bs)[BLD] = (__nv_bfloat16(*)[BLD])(sraw + ABYTES);

    int tid  = threadIdx.x;
    int wid  = tid >> 5;
    int lane = tid & 31;
    int m0   = blockIdx.x * 128;
    int cw   = wid % COLW;
    int rw   = wid / COLW;

    wmma::fragment<wmma::accumulator, 16, 16, 16, float> c[RF][CT];
#pragma unroll
    for (int rf = 0; rf < RF; rf++)
#pragma unroll
        for (int ct = 0; ct < CT; ct++)
            wmma::fill_fragment(c[rf][ct], 0.f);

    float4 pa[8];
#pragma unroll
    for (int t = 0; t < 8; t++) {
        int idx = tid + t * 256;
        int r   = idx >> 4;
        int c4  = (idx & 15) * 4;
        int row = m0 + r;
        pa[t] = make_float4(0.f, 0.f, 0.f, 0.f);
        if (row < M) pa[t] = *(const float4*)&A[(size_t)row * K + c4];
    }

    for (int ch = 0; ch < CH; ch++) {
        // A chunk: trunc split, packed 64-bit STS (hi pair + lo pair).
#pragma unroll
        for (int t = 0; t < 8; t++) {
            int idx = tid + t * 256;
            int r   = idx >> 4;
            int c4  = (idx & 15) * 4;
            float4 v = pa[t];
            unsigned bx = __float_as_uint(v.x) & 0xFFFF0000u;
            unsigned by = __float_as_uint(v.y) & 0xFFFF0000u;
            unsigned bz = __float_as_uint(v.z) & 0xFFFF0000u;
            unsigned bw = __float_as_uint(v.w) & 0xFFFF0000u;
            unsigned h01 = __byte_perm(__float_as_uint(v.x), __float_as_uint(v.y), 0x7632);
            unsigned h23 = __byte_perm(__float_as_uint(v.z), __float_as_uint(v.w), 0x7632);
            *(uint2*)&As[r][c4] = make_uint2(h01, h23);
            __nv_bfloat162 l01 =
                __floats2bfloat162_rn(v.x - __uint_as_float(bx), v.y - __uint_as_float(by));
            __nv_bfloat162 l23 =
                __floats2bfloat162_rn(v.z - __uint_as_float(bz), v.w - __uint_as_float(bw));
            *(uint2*)&As[r][64 + c4] =
                make_uint2(*(unsigned*)&l01, *(unsigned*)&l23);
        }
        // B chunk: hi rows [0,64), lo rows [64,128).
        {
            constexpr int R8 = NPAD / 8;
            int k0 = ch * 64;
            for (int i = tid; i < 64 * R8 * 2; i += 256) {
                int plane = i / (64 * R8);
                int j     = i % (64 * R8);
                int k     = j / R8;
                int b8    = j % R8;
                const __nv_bfloat16* sp = plane ? Bl : Bh;
                uint4 v = *(const uint4*)&sp[(size_t)(k0 + k) * NPAD + b8 * 8];
                *(uint4*)&Bs[plane * 64 + k][b8 * 8] = v;
            }
        }
        __syncthreads();

        if (ch + 1 < CH) {
            int k0n = (ch + 1) * 64;
#pragma unroll
            for (int t = 0; t < 8; t++) {
                int idx = tid + t * 256;
                int r   = idx >> 4;
                int c4  = (idx & 15) * 4;
                int row = m0 + r;
                pa[t] = make_float4(0.f, 0.f, 0.f, 0.f);
                if (row < M) pa[t] = *(const float4*)&A[(size_t)row * K + k0n + c4];
            }
        }

#pragma unroll
        for (int k16 = 0; k16 < 4; k16++) {
            wmma::fragment<wmma::matrix_a, 16, 16, 16, __nv_bfloat16, wmma::row_major> ah[RF], alo[RF];
#pragma unroll
            for (int rf = 0; rf < RF; rf++) {
                wmma::load_matrix_sync(ah[rf],  &As[rw * RPW + rf * 16][k16 * 16],      ALD);
                wmma::load_matrix_sync(alo[rf], &As[rw * RPW + rf * 16][64 + k16 * 16], ALD);
            }
#pragma unroll
            for (int ct = 0; ct < CT; ct++) {
                int cb = cw * CWID + ct * 16;
                wmma::fragment<wmma::matrix_b, 16, 16, 16, __nv_bfloat16, wmma::row_major> bh, bl;
                wmma::load_matrix_sync(bh, &Bs[k16 * 16][cb],      BLD);
                wmma::load_matrix_sync(bl, &Bs[64 + k16 * 16][cb], BLD);
#pragma unroll
                for (int rf = 0; rf < RF; rf++) {
                    wmma::mma_sync(c[rf][ct], ah[rf],  bh, c[rf][ct]);
                    wmma::mma_sync(c[rf][ct], ah[rf],  bl, c[rf][ct]);
                    wmma::mma_sync(c[rf][ct], alo[rf], bh, c[rf][ct]);
                }
            }
        }
        __syncthreads();
    }

    float (*Cbuf)[16][16] = (float(*)[16][16])sraw;
    float (*buf)[16] = Cbuf[wid];
    float* elbuf = (float*)(sraw + ABYTES);
    float* erbuf = elbuf + 128;
    if (tid < 128) { elbuf[tid] = 0.f; erbuf[tid] = 0.f; }
    __syncthreads();

#pragma unroll
    for (int rf = 0; rf < RF; rf++) {
        float elp = 0.f, erp = 0.f;
#pragma unroll
        for (int ct = 0; ct < CT; ct++) {
            wmma::store_matrix_sync(&buf[0][0], c[rf][ct], 16, wmma::mem_row_major);
            __syncwarp();
            int cb = cw * CWID + ct * 16;
            if (lane < 16) {
                int row = m0 + rw * RPW + rf * 16 + lane;
                if (row < M) {
#pragma unroll
                    for (int j = 0; j < 16; j++) {
                        int col = cb + j;
                        if (col < NOUT) {
                            float v = buf[lane][j];
                            elp += v * al[col];
                            erp += v * ar[col];
                        }
                    }
                }
            }
#pragma unroll
            for (int rep = 0; rep < 2; rep++) {
                int idx = lane + rep * 32;
                int r   = idx >> 2;
                int c4  = idx & 3;
                int row = m0 + rw * RPW + rf * 16 + r;
                int col = cb + c4 * 4;
                if (row < M && col < NOUT)
                    *(float4*)&Z[(size_t)row * NOUT + col] = *(float4*)&buf[r][c4 * 4];
            }
            __syncwarp();
        }
        if (lane < 16) {
            int lrow = rw * RPW + rf * 16 + lane;
            atomicAdd(&elbuf[lrow], elp);
            atomicAdd(&erbuf[lrow], erp);
        }
    }
    __syncthreads();
    if (tid < 128) {
        int row = m0 + tid;
        if (row < M) { g_el[row] = elbuf[tid]; g_er[row] = erbuf[tid]; }
    }
}

// --------------------- fused softmax + aggregation (round-9, FROZEN) -------

__global__ void fused_agg1_kernel(const float* __restrict__ Z, const float* __restrict__ b,
                                  float* __restrict__ H, int n, float neg_slope) {
    int node = (blockIdx.x * blockDim.x + threadIdx.x) >> 5;
    int lane = threadIdx.x & 31;
    if (node >= n) return;
    int start = g_off[node], end = g_off[node + 1];
    int deg   = end - start;
    float erd = g_er[node];

    float aL0 = 0.f, aL1 = 0.f, aH0 = 0.f, aH1 = 0.f, sum = 0.f;

    if (deg <= 32) {
        bool v = lane < deg;
        int   s = v ? g_srcs[start + lane] : 0;
        float e = v ? (g_el[s] + erd) : -3.4e38f;
        e = (e > 0.f) ? e : neg_slope * e;
        float m = warp_max(e);
        float w = v ? expf(e - m) : 0.f;
        sum = w;
        int cnt4 = (deg + 3) & ~3;
        for (int j = 0; j < cnt4; j += 4) {
            int   s0 = __shfl_sync(0xffffffffu, s, j);
            float w0 = __shfl_sync(0xffffffffu, w, j);
            int   s1 = __shfl_sync(0xffffffffu, s, j + 1);
            float w1 = __shfl_sync(0xffffffffu, w, j + 1);
            int   s2 = __shfl_sync(0xffffffffu, s, j + 2);
            float w2 = __shfl_sync(0xffffffffu, w, j + 2);
            int   s3 = __shfl_sync(0xffffffffu, s, j + 3);
            float w3 = __shfl_sync(0xffffffffu, w, j + 3);
            const float* z0 = Z + (long long)s0 * 64;
            const float* z1 = Z + (long long)s1 * 64;
            const float* z2 = Z + (long long)s2 * 64;
            const float* z3 = Z + (long long)s3 * 64;
            aL0 += w0 * z0[lane];  aH0 += w0 * z0[lane + 32];
            aL1 += w1 * z1[lane];  aH1 += w1 * z1[lane + 32];
            aL0 += w2 * z2[lane];  aH0 += w2 * z2[lane + 32];
            aL1 += w3 * z3[lane];  aH1 += w3 * z3[lane + 32];
        }
    } else {
        float m = -3.4e38f;
        for (int i = start + lane; i < end; i += 32) {
            float e = g_el[g_srcs[i]] + erd;
            e = (e > 0.f) ? e : neg_slope * e;
            m = fmaxf(m, e);
        }
        m = warp_max(m);
        for (int c = start; c < end; c += 32) {
            int idx = c + lane;
            bool v = idx < end;
            int   s = v ? g_srcs[idx] : 0;
            float e = v ? (g_el[s] + erd) : -3.4e38f;
            e = (e > 0.f) ? e : neg_slope * e;
            float w = v ? expf(e - m) : 0.f;
            sum += w;
            int cnt  = min(32, end - c);
            int cnt4 = (cnt + 3) & ~3;
            for (int j = 0; j < cnt4; j += 4) {
                int   s0 = __shfl_sync(0xffffffffu, s, j);
                float w0 = __shfl_sync(0xffffffffu, w, j);
                int   s1 = __shfl_sync(0xffffffffu, s, j + 1);
                float w1 = __shfl_sync(0xffffffffu, w, j + 1);
                int   s2 = __shfl_sync(0xffffffffu, s, j + 2);
                float w2 = __shfl_sync(0xffffffffu, w, j + 2);
                int   s3 = __shfl_sync(0xffffffffu, s, j + 3);
                float w3 = __shfl_sync(0xffffffffu, w, j + 3);
                const float* z0 = Z + (long long)s0 * 64;
                const float* z1 = Z + (long long)s1 * 64;
                const float* z2 = Z + (long long)s2 * 64;
                const float* z3 = Z + (long long)s3 * 64;
                aL0 += w0 * z0[lane];  aH0 += w0 * z0[lane + 32];
                aL1 += w1 * z1[lane];  aH1 += w1 * z1[lane + 32];
                aL0 += w2 * z2[lane];  aH0 += w2 * z2[lane + 32];
                aL1 += w3 * z3[lane];  aH1 += w3 * z3[lane + 32];
            }
        }
    }

    sum = warp_sum(sum);
    float sinv = (deg > 0) ? 1.f / sum : 0.f;
    float vL = (aL0 + aL1) * sinv + b[lane];
    float vH = (aH0 + aH1) * sinv + b[lane + 32];
    H[(long long)node * 64 + lane]      = (vL > 0.f) ? vL : 0.f;
    H[(long long)node * 64 + lane + 32] = (vH > 0.f) ? vH : 0.f;
}

__global__ void fused_agg2_kernel(const float* __restrict__ Z, const float* __restrict__ b,
                                  float* __restrict__ out, int n, float neg_slope) {
    int gw   = (blockIdx.x * blockDim.x + threadIdx.x) >> 5;
    int node = gw;
    int lane = threadIdx.x & 31;
    if (node >= n) return;
    int start = g_off[node], end = g_off[node + 1];
    int deg   = end - start;
    float erd = g_er[node];
    bool h1 = lane < 8;

    float accA = 0.f, accB = 0.f, acc1 = 0.f, sum = 0.f;

    if (deg <= 32) {
        bool v = lane < deg;
        int   s = v ? g_srcs[start + lane] : 0;
        float e = v ? (g_el[s] + erd) : -3.4e38f;
        e = (e > 0.f) ? e : neg_slope * e;
        float m = warp_max(e);
        float w = v ? expf(e - m) : 0.f;
        sum = w;
        int cnt8 = (deg + 7) & ~7;
        for (int j = 0; j < cnt8; j += 8) {
#pragma unroll
            for (int jj = 0; jj < 8; jj += 2) {
                int   s0 = __shfl_sync(0xffffffffu, s, j + jj);
                float w0 = __shfl_sync(0xffffffffu, w, j + jj);
                int   s1 = __shfl_sync(0xffffffffu, s, j + jj + 1);
                float w1 = __shfl_sync(0xffffffffu, w, j + jj + 1);
                const float* z0 = Z + (long long)s0 * 40;
                const float* z1 = Z + (long long)s1 * 40;
                accA += w0 * z0[lane];
                accB += w1 * z1[lane];
                if (h1) acc1 += w0 * z0[lane + 32] + w1 * z1[lane + 32];
            }
        }
    } else {
        float m = -3.4e38f;
        for (int i = start + lane; i < end; i += 32) {
            float e = g_el[g_srcs[i]] + erd;
            e = (e > 0.f) ? e : neg_slope * e;
            m = fmaxf(m, e);
        }
        m = warp_max(m);
        for (int c = start; c < end; c += 32) {
            int idx = c + lane;
            bool v = idx < end;
            int   s = v ? g_srcs[idx] : 0;
            float e = v ? (g_el[s] + erd) : -3.4e38f;
            e = (e > 0.f) ? e : neg_slope * e;
            float w = v ? expf(e - m) : 0.f;
            sum += w;
            int cnt  = min(32, end - c);
            int cnt8 = (cnt + 7) & ~7;
            for (int j = 0; j < cnt8; j += 8) {
#pragma unroll
                for (int jj = 0; jj < 8; jj += 2) {
                    int   s0 = __shfl_sync(0xffffffffu, s, j + jj);
                    float w0 = __shfl_sync(0xffffffffu, w, j + jj);
                    int   s1 = __shfl_sync(0xffffffffu, s, j + jj + 1);
                    float w1 = __shfl_sync(0xffffffffu, w, j + jj + 1);
                    const float* z0 = Z + (long long)s0 * 40;
                    const float* z1 = Z + (long long)s1 * 40;
                    accA += w0 * z0[lane];
                    accB += w1 * z1[lane];
                    if (h1) acc1 += w0 * z0[lane + 32] + w1 * z1[lane + 32];
                }
            }
        }
    }

    sum = warp_sum(sum);
    float sinv = (deg > 0) ? 1.f / sum : 0.f;
    float v0 = (accA + accB) * sinv + b[lane];
    float v1 = h1 ? (acc1 * sinv + b[lane + 32]) : -3.4e38f;

    float mx = warp_max(fmaxf(v0, v1));
    float se = warp_sum(expf(v0 - mx) + (h1 ? expf(v1 - mx) : 0.f));
    float lse = mx + logf(se);

    long long base = (long long)node * 40;
    out[base + lane] = v0 - lse;
    if (h1) out[base + lane + 32] = v1 - lse;
}

// ----------------------------- host launch ---------------------------------

extern "C" void kernel_launch(void* const* d_in, const int* in_sizes, int n_in,
                              void* d_out, int out_size) {
    const float* feat = (const float*)d_in[0];
    const int*   src  = (const int*)  d_in[1];
    const int*   dst  = (const int*)  d_in[2];
    const float* W1   = (const float*)d_in[3];
    const float* b1   = (const float*)d_in[4];
    const float* al1  = (const float*)d_in[5];
    const float* ar1  = (const float*)d_in[6];
    const float* W2   = (const float*)d_in[7];
    const float* b2   = (const float*)d_in[8];
    const float* al2  = (const float*)d_in[9];
    const float* ar2  = (const float*)d_in[10];
    float* out = (float*)d_out;

    const int IN = 256;
    int n = in_sizes[0] / IN;   // 100000
    int E = in_sizes[1];        // 1600000

    float* zp; cudaGetSymbolAddress((void**)&zp, g_z);
    float* hp; cudaGetSymbolAddress((void**)&hp, g_h);
    __nv_bfloat16 *bt1h, *bt1l, *bt2h, *bt2l;
    cudaGetSymbolAddress((void**)&bt1h, g_bt1h);
    cudaGetSymbolAddress((void**)&bt1l, g_bt1l);
    cudaGetSymbolAddress((void**)&bt2h, g_bt2h);
    cudaGetSymbolAddress((void**)&bt2l, g_bt2l);

    const float NEG_SLOPE = 0.2f;
    int mb128 = (n + 127) / 128;
    int nb_scan = (n + SCAN_CHUNK - 1) / SCAN_CHUNK;

    // gemm1 at stream launch index 3 (profiler's capture slot).
    wconv_kernel<<<(256 * 64 + 255) / 256, 256>>>(W1, 256, 64, 64, bt1h, bt1l);         // 0
    hist_kernel<<<(E + 255) / 256, 256>>>(dst, E);                                      // 1
    scan_phase1<<<nb_scan, SCAN_CHUNK>>>(n);                                            // 2
    gemm_wmma_kernel<256, 64, 64, 2><<<mb128, 256>>>(feat, bt1h, bt1l, al1, ar1, zp, n);// 3 <- profiled
    wconv_kernel<<<(64 * 48 + 255) / 256, 256>>>(W2, 64, 40, 48, bt2h, bt2l);           // 4
    scan_phase2<<<1, 32>>>(nb_scan);                                                    // 5
    scan_phase3<<<(n + 255) / 256, 256>>>(n);                                           // 6
    scatter_kernel<<<(E + 255) / 256, 256>>>(src, dst, E);                              // 7

    fused_agg1_kernel<<<(n * 32 + 255) / 256, 256>>>(zp, b1, hp, n, NEG_SLOPE);         // 8
    gemm_wmma_kernel<64, 40, 48, 1><<<mb128, 256>>>(hp, bt2h, bt2l, al2, ar2, zp, n);   // 9
    fused_agg2_kernel<<<(n * 32 + 255) / 256, 256>>>(zp, b2, out, n, NEG_SLOPE);        // 10
}

// round 14
// speedup vs baseline: 1.0969x; 1.0583x over previous
#include <cuda_runtime.h>
#include <cuda_bf16.h>
#include <mma.h>
#include <math.h>
#include <stdint.h>

using namespace nvcuda;

// ---------------------------------------------------------------------------
// DenseGAT: 2-layer GAT, N=100000 nodes, E=1600000 edges, 256 -> 64 -> 40
// Dual-stream fork/join graph: CSR build overlaps gemm1.
// bf16-split WMMA GEMM (frozen) + fused logits; round-9 gather agg (frozen).
// ---------------------------------------------------------------------------

#define MAX_NODES 100000
#define MAX_EDGES 1600000
#define SCAN_CHUNK 512
#define MAX_BLOCKS_SCAN 256

__device__ float g_z   [MAX_NODES * 64];
__device__ float g_h   [MAX_NODES * 64];
__device__ float g_el  [MAX_NODES];
__device__ float g_er  [MAX_NODES];
__device__ int   g_deg [MAX_NODES];
__device__ int   g_scan[MAX_NODES];
__device__ int   g_off [MAX_NODES + 1];
__device__ int   g_cur [MAX_NODES];
__device__ int   g_srcs[MAX_EDGES];
__device__ int   g_bsum[MAX_BLOCKS_SCAN];
__device__ int   g_boff[MAX_BLOCKS_SCAN];

// bf16 hi/lo W planes, row-major padded: layer1 [256][64], layer2 [64][48]
__device__ __align__(16) __nv_bfloat16 g_bt1h[256 * 64];
__device__ __align__(16) __nv_bfloat16 g_bt1l[256 * 64];
__device__ __align__(16) __nv_bfloat16 g_bt2h[64 * 48];
__device__ __align__(16) __nv_bfloat16 g_bt2l[64 * 48];

// ---- side stream + fork/join events (created at load time, pre-checkpoint,
// no device-memory allocation involved) ----
static cudaStream_t g_s2;
static cudaEvent_t  g_eFork, g_eJoin;
namespace {
struct StreamInit {
    StreamInit() {
        cudaStreamCreateWithFlags(&g_s2, cudaStreamNonBlocking);
        cudaEventCreateWithFlags(&g_eFork, cudaEventDisableTiming);
        cudaEventCreateWithFlags(&g_eJoin, cudaEventDisableTiming);
    }
};
static StreamInit g_streamInit;
}

__device__ __forceinline__ float warp_max(float v) {
#pragma unroll
    for (int o = 16; o > 0; o >>= 1)
        v = fmaxf(v, __shfl_xor_sync(0xffffffffu, v, o));
    return v;
}
__device__ __forceinline__ float warp_sum(float v) {
#pragma unroll
    for (int o = 16; o > 0; o >>= 1)
        v += __shfl_xor_sync(0xffffffffu, v, o);
    return v;
}

// ----------------------------- W convert ----------------------------------

__global__ void wconv_kernel(const float* __restrict__ W, int K, int NOUT, int NPAD,
                             __nv_bfloat16* __restrict__ oh, __nv_bfloat16* __restrict__ ol) {
    int idx = blockIdx.x * blockDim.x + threadIdx.x;
    if (idx >= K * NPAD) return;
    int k = idx / NPAD;
    int n = idx % NPAD;
    float v = (n < NOUT) ? W[k * NOUT + n] : 0.f;
    __nv_bfloat16 h = __float2bfloat16(v);
    __nv_bfloat16 l = __float2bfloat16(v - __bfloat162float(h));
    oh[idx] = h;
    ol[idx] = l;
}

// ----------------------------- CSR build ----------------------------------

__global__ void hist_kernel(const int* __restrict__ dst, int E) {
    int i = blockIdx.x * blockDim.x + threadIdx.x;
    if (i < E) atomicAdd(&g_deg[dst[i]], 1);
}

__global__ void scan_phase1(int n) {
    __shared__ int sm[SCAN_CHUNK];
    int i = blockIdx.x * SCAN_CHUNK + threadIdx.x;
    int d = (i < n) ? g_deg[i] : 0;
    if (i < n) g_deg[i] = 0;
    sm[threadIdx.x] = d;
    __syncthreads();
#pragma unroll
    for (int o = 1; o < SCAN_CHUNK; o <<= 1) {
        int t = (threadIdx.x >= o) ? sm[threadIdx.x - o] : 0;
        __syncthreads();
        sm[threadIdx.x] += t;
        __syncthreads();
    }
    if (i < n) g_scan[i] = sm[threadIdx.x];
    if (threadIdx.x == SCAN_CHUNK - 1) g_bsum[blockIdx.x] = sm[SCAN_CHUNK - 1];
}

__global__ void scan_phase2(int nb) {
    int lane = threadIdx.x;
    int base = lane * 8;
    int v[8];
    int s = 0;
#pragma unroll
    for (int j = 0; j < 8; j++) {
        int x = (base + j < nb) ? g_bsum[base + j] : 0;
        v[j] = s;
        s += x;
    }
    int t = s;
#pragma unroll
    for (int o = 1; o < 32; o <<= 1) {
        int u = __shfl_up_sync(0xffffffffu, t, o);
        if (lane >= o) t += u;
    }
    int excl = t - s;
#pragma unroll
    for (int j = 0; j < 8; j++)
        if (base + j < nb) g_boff[base + j] = excl + v[j];
}

__global__ void scan_phase3(int n) {
    int i = blockIdx.x * blockDim.x + threadIdx.x;
    if (i < n) {
        int v = g_scan[i] + g_boff[i >> 9];
        g_off[i + 1] = v;
        if (i + 1 < n) g_cur[i + 1] = v;
    }
    if (i == 0) { g_off[0] = 0; g_cur[0] = 0; }
}

__global__ void scatter_kernel(const int* __restrict__ src, const int* __restrict__ dst, int E) {
    int i = blockIdx.x * blockDim.x + threadIdx.x;
    if (i >= E) return;
    int pos = atomicAdd(&g_cur[dst[i]], 1);
    g_srcs[pos] = src[i];
}

// ----------------------------- WMMA GEMM + fused logits --------------------
// (frozen: measured ~64.5-64.8us for layer 1)

template<int K, int NOUT, int NPAD, int COLW>
__global__ void __launch_bounds__(256, 2)
gemm_wmma_kernel(const float* __restrict__ A,
                 const __nv_bfloat16* __restrict__ Bh,
                 const __nv_bfloat16* __restrict__ Bl,
                 const float* __restrict__ al, const float* __restrict__ ar,
                 float* __restrict__ Z, int M) {
    constexpr int CH  = K / 64;
    constexpr int ROWG = 8 / COLW;
    constexpr int RPW  = 128 / ROWG;
    constexpr int RF   = RPW / 16;
    constexpr int CT   = NPAD / 16 / COLW;
    constexpr int CWID = NPAD / COLW;
    constexpr int ALD = 136;
    constexpr int BLD = NPAD + 8;
    constexpr int ABYTES = 128 * ALD * 2;

    __shared__ __align__(16) unsigned char sraw[ABYTES + 128 * BLD * 2];
    __nv_bfloat16 (*As)[ALD] = (__nv_bfloat16(*)[ALD])sraw;
    __nv_bfloat16 (*Bs)[BLD] = (__nv_bfloat16(*)[BLD])(sraw + ABYTES);

    int tid  = threadIdx.x;
    int wid  = tid >> 5;
    int lane = tid & 31;
    int m0   = blockIdx.x * 128;
    int cw   = wid % COLW;
    int rw   = wid / COLW;

    wmma::fragment<wmma::accumulator, 16, 16, 16, float> c[RF][CT];
#pragma unroll
    for (int rf = 0; rf < RF; rf++)
#pragma unroll
        for (int ct = 0; ct < CT; ct++)
            wmma::fill_fragment(c[rf][ct], 0.f);

    float4 pa[8];
#pragma unroll
    for (int t = 0; t < 8; t++) {
        int idx = tid + t * 256;
        int r   = idx >> 4;
        int c4  = (idx & 15) * 4;
        int row = m0 + r;
        pa[t] = make_float4(0.f, 0.f, 0.f, 0.f);
        if (row < M) pa[t] = *(const float4*)&A[(size_t)row * K + c4];
    }

    for (int ch = 0; ch < CH; ch++) {
#pragma unroll
        for (int t = 0; t < 8; t++) {
            int idx = tid + t * 256;
            int r   = idx >> 4;
            int c4  = (idx & 15) * 4;
            float4 v = pa[t];
            unsigned bx = __float_as_uint(v.x) & 0xFFFF0000u;
            unsigned by = __float_as_uint(v.y) & 0xFFFF0000u;
            unsigned bz = __float_as_uint(v.z) & 0xFFFF0000u;
            unsigned bw = __float_as_uint(v.w) & 0xFFFF0000u;
            unsigned h01 = __byte_perm(__float_as_uint(v.x), __float_as_uint(v.y), 0x7632);
            unsigned h23 = __byte_perm(__float_as_uint(v.z), __float_as_uint(v.w), 0x7632);
            *(uint2*)&As[r][c4] = make_uint2(h01, h23);
            __nv_bfloat162 l01 =
                __floats2bfloat162_rn(v.x - __uint_as_float(bx), v.y - __uint_as_float(by));
            __nv_bfloat162 l23 =
                __floats2bfloat162_rn(v.z - __uint_as_float(bz), v.w - __uint_as_float(bw));
            *(uint2*)&As[r][64 + c4] =
                make_uint2(*(unsigned*)&l01, *(unsigned*)&l23);
        }
        {
            constexpr int R8 = NPAD / 8;
            int k0 = ch * 64;
            for (int i = tid; i < 64 * R8 * 2; i += 256) {
                int plane = i / (64 * R8);
                int j     = i % (64 * R8);
                int k     = j / R8;
                int b8    = j % R8;
                const __nv_bfloat16* sp = plane ? Bl : Bh;
                uint4 v = *(const uint4*)&sp[(size_t)(k0 + k) * NPAD + b8 * 8];
                *(uint4*)&Bs[plane * 64 + k][b8 * 8] = v;
            }
        }
        __syncthreads();

        if (ch + 1 < CH) {
            int k0n = (ch + 1) * 64;
#pragma unroll
            for (int t = 0; t < 8; t++) {
                int idx = tid + t * 256;
                int r   = idx >> 4;
                int c4  = (idx & 15) * 4;
                int row = m0 + r;
                pa[t] = make_float4(0.f, 0.f, 0.f, 0.f);
                if (row < M) pa[t] = *(const float4*)&A[(size_t)row * K + k0n + c4];
            }
        }

#pragma unroll
        for (int k16 = 0; k16 < 4; k16++) {
            wmma::fragment<wmma::matrix_a, 16, 16, 16, __nv_bfloat16, wmma::row_major> ah[RF], alo[RF];
#pragma unroll
            for (int rf = 0; rf < RF; rf++) {
                wmma::load_matrix_sync(ah[rf],  &As[rw * RPW + rf * 16][k16 * 16],      ALD);
                wmma::load_matrix_sync(alo[rf], &As[rw * RPW + rf * 16][64 + k16 * 16], ALD);
            }
#pragma unroll
            for (int ct = 0; ct < CT; ct++) {
                int cb = cw * CWID + ct * 16;
                wmma::fragment<wmma::matrix_b, 16, 16, 16, __nv_bfloat16, wmma::row_major> bh, bl;
                wmma::load_matrix_sync(bh, &Bs[k16 * 16][cb],      BLD);
                wmma::load_matrix_sync(bl, &Bs[64 + k16 * 16][cb], BLD);
#pragma unroll
                for (int rf = 0; rf < RF; rf++) {
                    wmma::mma_sync(c[rf][ct], ah[rf],  bh, c[rf][ct]);
                    wmma::mma_sync(c[rf][ct], ah[rf],  bl, c[rf][ct]);
                    wmma::mma_sync(c[rf][ct], alo[rf], bh, c[rf][ct]);
                }
            }
        }
        __syncthreads();
    }

    float (*Cbuf)[16][16] = (float(*)[16][16])sraw;
    float (*buf)[16] = Cbuf[wid];
    float* elbuf = (float*)(sraw + ABYTES);
    float* erbuf = elbuf + 128;
    if (tid < 128) { elbuf[tid] = 0.f; erbuf[tid] = 0.f; }
    __syncthreads();

#pragma unroll
    for (int rf = 0; rf < RF; rf++) {
        float elp = 0.f, erp = 0.f;
#pragma unroll
        for (int ct = 0; ct < CT; ct++) {
            wmma::store_matrix_sync(&buf[0][0], c[rf][ct], 16, wmma::mem_row_major);
            __syncwarp();
            int cb = cw * CWID + ct * 16;
            if (lane < 16) {
                int row = m0 + rw * RPW + rf * 16 + lane;
                if (row < M) {
#pragma unroll
                    for (int j = 0; j < 16; j++) {
                        int col = cb + j;
                        if (col < NOUT) {
                            float v = buf[lane][j];
                            elp += v * al[col];
                            erp += v * ar[col];
                        }
                    }
                }
            }
#pragma unroll
            for (int rep = 0; rep < 2; rep++) {
                int idx = lane + rep * 32;
                int r   = idx >> 2;
                int c4  = idx & 3;
                int row = m0 + rw * RPW + rf * 16 + r;
                int col = cb + c4 * 4;
                if (row < M && col < NOUT)
                    *(float4*)&Z[(size_t)row * NOUT + col] = *(float4*)&buf[r][c4 * 4];
            }
            __syncwarp();
        }
        if (lane < 16) {
            int lrow = rw * RPW + rf * 16 + lane;
            atomicAdd(&elbuf[lrow], elp);
            atomicAdd(&erbuf[lrow], erp);
        }
    }
    __syncthreads();
    if (tid < 128) {
        int row = m0 + tid;
        if (row < M) { g_el[row] = elbuf[tid]; g_er[row] = erbuf[tid]; }
    }
}

// --------------------- fused softmax + aggregation (round-9, FROZEN) -------

__global__ void fused_agg1_kernel(const float* __restrict__ Z, const float* __restrict__ b,
                                  float* __restrict__ H, int n, float neg_slope) {
    int node = (blockIdx.x * blockDim.x + threadIdx.x) >> 5;
    int lane = threadIdx.x & 31;
    if (node >= n) return;
    int start = g_off[node], end = g_off[node + 1];
    int deg   = end - start;
    float erd = g_er[node];

    float aL0 = 0.f, aL1 = 0.f, aH0 = 0.f, aH1 = 0.f, sum = 0.f;

    if (deg <= 32) {
        bool v = lane < deg;
        int   s = v ? g_srcs[start + lane] : 0;
        float e = v ? (g_el[s] + erd) : -3.4e38f;
        e = (e > 0.f) ? e : neg_slope * e;
        float m = warp_max(e);
        float w = v ? expf(e - m) : 0.f;
        sum = w;
        int cnt4 = (deg + 3) & ~3;
        for (int j = 0; j < cnt4; j += 4) {
            int   s0 = __shfl_sync(0xffffffffu, s, j);
            float w0 = __shfl_sync(0xffffffffu, w, j);
            int   s1 = __shfl_sync(0xffffffffu, s, j + 1);
            float w1 = __shfl_sync(0xffffffffu, w, j + 1);
            int   s2 = __shfl_sync(0xffffffffu, s, j + 2);
            float w2 = __shfl_sync(0xffffffffu, w, j + 2);
            int   s3 = __shfl_sync(0xffffffffu, s, j + 3);
            float w3 = __shfl_sync(0xffffffffu, w, j + 3);
            const float* z0 = Z + (long long)s0 * 64;
            const float* z1 = Z + (long long)s1 * 64;
            const float* z2 = Z + (long long)s2 * 64;
            const float* z3 = Z + (long long)s3 * 64;
            aL0 += w0 * z0[lane];  aH0 += w0 * z0[lane + 32];
            aL1 += w1 * z1[lane];  aH1 += w1 * z1[lane + 32];
            aL0 += w2 * z2[lane];  aH0 += w2 * z2[lane + 32];
            aL1 += w3 * z3[lane];  aH1 += w3 * z3[lane + 32];
        }
    } else {
        float m = -3.4e38f;
        for (int i = start + lane; i < end; i += 32) {
            float e = g_el[g_srcs[i]] + erd;
            e = (e > 0.f) ? e : neg_slope * e;
            m = fmaxf(m, e);
        }
        m = warp_max(m);
        for (int c = start; c < end; c += 32) {
            int idx = c + lane;
            bool v = idx < end;
            int   s = v ? g_srcs[idx] : 0;
            float e = v ? (g_el[s] + erd) : -3.4e38f;
            e = (e > 0.f) ? e : neg_slope * e;
            float w = v ? expf(e - m) : 0.f;
            sum += w;
            int cnt  = min(32, end - c);
            int cnt4 = (cnt + 3) & ~3;
            for (int j = 0; j < cnt4; j += 4) {
                int   s0 = __shfl_sync(0xffffffffu, s, j);
                float w0 = __shfl_sync(0xffffffffu, w, j);
                int   s1 = __shfl_sync(0xffffffffu, s, j + 1);
                float w1 = __shfl_sync(0xffffffffu, w, j + 1);
                int   s2 = __shfl_sync(0xffffffffu, s, j + 2);
                float w2 = __shfl_sync(0xffffffffu, w, j + 2);
                int   s3 = __shfl_sync(0xffffffffu, s, j + 3);
                float w3 = __shfl_sync(0xffffffffu, w, j + 3);
                const float* z0 = Z + (long long)s0 * 64;
                const float* z1 = Z + (long long)s1 * 64;
                const float* z2 = Z + (long long)s2 * 64;
                const float* z3 = Z + (long long)s3 * 64;
                aL0 += w0 * z0[lane];  aH0 += w0 * z0[lane + 32];
                aL1 += w1 * z1[lane];  aH1 += w1 * z1[lane + 32];
                aL0 += w2 * z2[lane];  aH0 += w2 * z2[lane + 32];
                aL1 += w3 * z3[lane];  aH1 += w3 * z3[lane + 32];
            }
        }
    }

    sum = warp_sum(sum);
    float sinv = (deg > 0) ? 1.f / sum : 0.f;
    float vL = (aL0 + aL1) * sinv + b[lane];
    float vH = (aH0 + aH1) * sinv + b[lane + 32];
    H[(long long)node * 64 + lane]      = (vL > 0.f) ? vL : 0.f;
    H[(long long)node * 64 + lane + 32] = (vH > 0.f) ? vH : 0.f;
}

__global__ void fused_agg2_kernel(const float* __restrict__ Z, const float* __restrict__ b,
                                  float* __restrict__ out, int n, float neg_slope) {
    int gw   = (blockIdx.x * blockDim.x + threadIdx.x) >> 5;
    int node = gw;
    int lane = threadIdx.x & 31;
    if (node >= n) return;
    int start = g_off[node], end = g_off[node + 1];
    int deg   = end - start;
    float erd = g_er[node];
    bool h1 = lane < 8;

    float accA = 0.f, accB = 0.f, acc1 = 0.f, sum = 0.f;

    if (deg <= 32) {
        bool v = lane < deg;
        int   s = v ? g_srcs[start + lane] : 0;
        float e = v ? (g_el[s] + erd) : -3.4e38f;
        e = (e > 0.f) ? e : neg_slope * e;
        float m = warp_max(e);
        float w = v ? expf(e - m) : 0.f;
        sum = w;
        int cnt8 = (deg + 7) & ~7;
        for (int j = 0; j < cnt8; j += 8) {
#pragma unroll
            for (int jj = 0; jj < 8; jj += 2) {
                int   s0 = __shfl_sync(0xffffffffu, s, j + jj);
                float w0 = __shfl_sync(0xffffffffu, w, j + jj);
                int   s1 = __shfl_sync(0xffffffffu, s, j + jj + 1);
                float w1 = __shfl_sync(0xffffffffu, w, j + jj + 1);
                const float* z0 = Z + (long long)s0 * 40;
                const float* z1 = Z + (long long)s1 * 40;
                accA += w0 * z0[lane];
                accB += w1 * z1[lane];
                if (h1) acc1 += w0 * z0[lane + 32] + w1 * z1[lane + 32];
            }
        }
    } else {
        float m = -3.4e38f;
        for (int i = start + lane; i < end; i += 32) {
            float e = g_el[g_srcs[i]] + erd;
            e = (e > 0.f) ? e : neg_slope * e;
            m = fmaxf(m, e);
        }
        m = warp_max(m);
        for (int c = start; c < end; c += 32) {
            int idx = c + lane;
            bool v = idx < end;
            int   s = v ? g_srcs[idx] : 0;
            float e = v ? (g_el[s] + erd) : -3.4e38f;
            e = (e > 0.f) ? e : neg_slope * e;
            float w = v ? expf(e - m) : 0.f;
            sum += w;
            int cnt  = min(32, end - c);
            int cnt8 = (cnt + 7) & ~7;
            for (int j = 0; j < cnt8; j += 8) {
#pragma unroll
                for (int jj = 0; jj < 8; jj += 2) {
                    int   s0 = __shfl_sync(0xffffffffu, s, j + jj);
                    float w0 = __shfl_sync(0xffffffffu, w, j + jj);
                    int   s1 = __shfl_sync(0xffffffffu, s, j + jj + 1);
                    float w1 = __shfl_sync(0xffffffffu, w, j + jj + 1);
                    const float* z0 = Z + (long long)s0 * 40;
                    const float* z1 = Z + (long long)s1 * 40;
                    accA += w0 * z0[lane];
                    accB += w1 * z1[lane];
                    if (h1) acc1 += w0 * z0[lane + 32] + w1 * z1[lane + 32];
                }
            }
        }
    }

    sum = warp_sum(sum);
    float sinv = (deg > 0) ? 1.f / sum : 0.f;
    float v0 = (accA + accB) * sinv + b[lane];
    float v1 = h1 ? (acc1 * sinv + b[lane + 32]) : -3.4e38f;

    float mx = warp_max(fmaxf(v0, v1));
    float se = warp_sum(expf(v0 - mx) + (h1 ? expf(v1 - mx) : 0.f));
    float lse = mx + logf(se);

    long long base = (long long)node * 40;
    out[base + lane] = v0 - lse;
    if (h1) out[base + lane + 32] = v1 - lse;
}

// ----------------------------- host launch ---------------------------------

extern "C" void kernel_launch(void* const* d_in, const int* in_sizes, int n_in,
                              void* d_out, int out_size) {
    const float* feat = (const float*)d_in[0];
    const int*   src  = (const int*)  d_in[1];
    const int*   dst  = (const int*)  d_in[2];
    const float* W1   = (const float*)d_in[3];
    const float* b1   = (const float*)d_in[4];
    const float* al1  = (const float*)d_in[5];
    const float* ar1  = (const float*)d_in[6];
    const float* W2   = (const float*)d_in[7];
    const float* b2   = (const float*)d_in[8];
    const float* al2  = (const float*)d_in[9];
    const float* ar2  = (const float*)d_in[10];
    float* out = (float*)d_out;

    const int IN = 256;
    int n = in_sizes[0] / IN;   // 100000
    int E = in_sizes[1];        // 1600000

    float* zp; cudaGetSymbolAddress((void**)&zp, g_z);
    float* hp; cudaGetSymbolAddress((void**)&hp, g_h);
    __nv_bfloat16 *bt1h, *bt1l, *bt2h, *bt2l;
    cudaGetSymbolAddress((void**)&bt1h, g_bt1h);
    cudaGetSymbolAddress((void**)&bt1l, g_bt1l);
    cudaGetSymbolAddress((void**)&bt2h, g_bt2h);
    cudaGetSymbolAddress((void**)&bt2l, g_bt2l);

    const float NEG_SLOPE = 0.2f;
    int mb128 = (n + 127) / 128;
    int nb_scan = (n + SCAN_CHUNK - 1) / SCAN_CHUNK;

    // ---- fork: CSR build + wconv2 run on g_s2, concurrent with gemm1 ----
    cudaEventRecord(g_eFork, 0);
    cudaStreamWaitEvent(g_s2, g_eFork, 0);

    hist_kernel<<<(E + 255) / 256, 256, 0, g_s2>>>(dst, E);                        // 0
    scan_phase1<<<nb_scan, SCAN_CHUNK, 0, g_s2>>>(n);                              // 1
    wconv_kernel<<<(256 * 64 + 255) / 256, 256>>>(W1, 256, 64, 64, bt1h, bt1l);    // 2 (main)
    gemm_wmma_kernel<256, 64, 64, 2><<<mb128, 256>>>(feat, bt1h, bt1l,
                                                     al1, ar1, zp, n);             // 3 (main) <- profiled
    scan_phase2<<<1, 32, 0, g_s2>>>(nb_scan);                                      // 4
    scan_phase3<<<(n + 255) / 256, 256, 0, g_s2>>>(n);                             // 5
    scatter_kernel<<<(E + 255) / 256, 256, 0, g_s2>>>(src, dst, E);                // 6
    wconv_kernel<<<(64 * 48 + 255) / 256, 256, 0, g_s2>>>(W2, 64, 40, 48,
                                                          bt2h, bt2l);             // 7

    // ---- join: main stream waits for CSR + wconv2 ----
    cudaEventRecord(g_eJoin, g_s2);
    cudaStreamWaitEvent(0, g_eJoin, 0);

    fused_agg1_kernel<<<(n * 32 + 255) / 256, 256>>>(zp, b1, hp, n, NEG_SLOPE);       // 8
    gemm_wmma_kernel<64, 40, 48, 1><<<mb128, 256>>>(hp, bt2h, bt2l, al2, ar2, zp, n); // 9
    fused_agg2_kernel<<<(n * 32 + 255) / 256, 256>>>(zp, b2, out, n, NEG_SLOPE);      // 10
}